// round 9
// baseline (speedup 1.0000x reference)
#include <cuda_runtime.h>
#include <math.h>

#define NREP 128
#define MNBR 48
#define NTH  512
#define ASTR 132          // multiple of 4 -> every row 16B-aligned -> float4 LDS/STS
#define XSTR 132

// shared layout (float offsets). XT ALIASES Ash rows 0..47.
#define OFF_A    0
#define OFF_SCAL 16896    // 128*132
#define OFF_DIAG 16944
#define OFF_INVD 17072
#define SMEM_FLOATS 17104 // 66.8 KB -> 2 CTAs/SM @ 512 thr = 32 warps/SM

__device__ __forceinline__ unsigned long long dup2(float x) {
    unsigned long long r;
    asm("mov.b64 %0, {%1, %1};" : "=l"(r) : "r"(__float_as_uint(x)));
    return r;
}
__device__ __forceinline__ unsigned long long pack2(float x, float y) {
    unsigned long long r;
    asm("mov.b64 %0, {%1, %2};" : "=l"(r) : "r"(__float_as_uint(x)), "r"(__float_as_uint(y)));
    return r;
}
__device__ __forceinline__ void unpack2(unsigned long long v, float &x, float &y) {
    unsigned lo, hi;
    asm("mov.b64 {%0, %1}, %2;" : "=r"(lo), "=r"(hi) : "l"(v));
    x = __uint_as_float(lo); y = __uint_as_float(hi);
}
// packed dual-FMA (sm_103a FFMA2) -- 2x fp32 throughput vs scalar FFMA
__device__ __forceinline__ void ffma2(unsigned long long &d, unsigned long long a, unsigned long long b) {
    asm("fma.rn.f32x2 %0, %1, %2, %3;" : "=l"(d) : "l"(a), "l"(b), "l"(d));
}

// gram accumulation over k in [K0,K1) for a 4x4 microtile
template<int K0, int K1>
__device__ __forceinline__ void gram_acc(const float* __restrict__ XT, int i0, int j0,
                                         unsigned long long acc[4][2]) {
    #pragma unroll
    for (int r = 0; r < 4; ++r) { acc[r][0] = 0ull; acc[r][1] = 0ull; }
    #pragma unroll
    for (int k = K0; k < K1; ++k) {
        const float* row = XT + k * XSTR;
        float4 a4 = *(const float4*)(row + i0);
        float4 b4 = *(const float4*)(row + j0);
        unsigned long long bu0 = pack2(b4.x, b4.y);
        unsigned long long bu1 = pack2(b4.z, b4.w);
        unsigned long long a0 = dup2(a4.x), a1 = dup2(a4.y);
        unsigned long long a2 = dup2(a4.z), a3 = dup2(a4.w);
        ffma2(acc[0][0], a0, bu0); ffma2(acc[0][1], a0, bu1);
        ffma2(acc[1][0], a1, bu0); ffma2(acc[1][1], a1, bu1);
        ffma2(acc[2][0], a2, bu0); ffma2(acc[2][1], a2, bu1);
        ffma2(acc[3][0], a3, bu0); ffma2(acc[3][1], a3, bu1);
    }
}

// full-K gram with two independent accumulator chains (2x ILP), result as 16 floats
__device__ __forceinline__ void gram_full(const float* __restrict__ XT, int i0, int j0,
                                          float o[4][4]) {
    unsigned long long acc1[4][2], acc2[4][2];
    gram_acc<0, 24>(XT, i0, j0, acc1);
    gram_acc<24, MNBR>(XT, i0, j0, acc2);
    #pragma unroll
    for (int r = 0; r < 4; ++r) {
        float p0, p1, p2, p3, q0, q1, q2, q3;
        unpack2(acc1[r][0], p0, p1); unpack2(acc1[r][1], p2, p3);
        unpack2(acc2[r][0], q0, q1); unpack2(acc2[r][1], q2, q3);
        o[r][0] = p0 + q0; o[r][1] = p1 + q1; o[r][2] = p2 + q2; o[r][3] = p3 + q3;
    }
}

// in-register Matern transform of a 4x4 microtile (raw gram -> final g values)
__device__ __forceinline__ void xform_tile(float o[4][4], int i0, int j0,
                                           const float* __restrict__ diag_s,
                                           float ils2, float sig2, float inug) {
    #pragma unroll
    for (int r = 0; r < 4; ++r) {
        float di = diag_s[i0 + r];
        #pragma unroll
        for (int c = 0; c < 4; ++c) {
            float dj  = diag_s[j0 + c];
            float lin = o[r][c];
            float sq  = (di + dj - 2.0f * lin) * ils2;
            float d   = sqrtf(fmaxf(sq, 0.0f));
            float s3  = 1.7320508075688772f * d;
            float mat = (1.0f + s3) * __expf(-s3);
            float val = (lin + sig2 * mat) * inug;
            if (i0 + r == j0 + c) val += 1.0f;
            o[r][c] = val;
        }
    }
}

__device__ __forceinline__ void store_tile_g(float* __restrict__ gout, int i0, int j0,
                                             float o[4][4]) {
    #pragma unroll
    for (int r = 0; r < 4; ++r)
        *(float4*)(gout + (i0 + r) * 128 + j0) = make_float4(o[r][0], o[r][1], o[r][2], o[r][3]);
}
__device__ __forceinline__ void store_tile_s(float* __restrict__ Ash, int i0, int j0,
                                             float o[4][4]) {
    #pragma unroll
    for (int r = 0; r < 4; ++r)
        *(float4*)(Ash + (i0 + r) * ASTR + j0) = make_float4(o[r][0], o[r][1], o[r][2], o[r][3]);
}

extern "C" __global__ void __launch_bounds__(NTH, 2)
tmap_kernel(const float* __restrict__ aug,
            const float* __restrict__ theta,
            const float* __restrict__ scales,
            const float* __restrict__ nug,
            const int*   __restrict__ bidx,
            float* __restrict__ out,
            int n_loc)
{
    extern __shared__ float sm[];
    float* Ash    = sm + OFF_A;
    float* XT     = sm + OFF_A;      // aliased with Ash rows 0..47
    float* scal_s = sm + OFF_SCAL;
    float* diag_s = sm + OFF_DIAG;
    float* invd_s = sm + OFF_INVD;

    const int n   = blockIdx.x;
    const int tid = threadIdx.x;
    float* gout = out + (size_t)n * 16384;
    float* cout = out + (size_t)n_loc * 16384 + (size_t)n * 16384;

    // batch_idx == 0  ->  g = I, chol = I
    if (bidx[n] == 0) {
        for (int q4 = tid; q4 < 4096; q4 += NTH) {
            int idx = q4 * 4;
            int i = idx >> 7, j = idx & 127;
            float4 v = make_float4(i == j ? 1.f : 0.f, i == j + 1 ? 1.f : 0.f,
                                   i == j + 2 ? 1.f : 0.f, i == j + 3 ? 1.f : 0.f);
            ((float4*)gout)[q4] = v;
            ((float4*)cout)[q4] = v;
        }
        return;
    }

    // ---- per-column scaling: scal_k = exp(-0.5*k*exp(theta2)), k=1..48 ----
    const float e2 = __expf(theta[2]);
    if (tid < MNBR) scal_s[tid] = __expf(-0.5f * (float)(tid + 1) * e2);
    __syncthreads();

    // ---- load xs transposed into shared: XT[k][r] = aug[r,n,k+1]*scal_k ----
    for (int idx = tid; idx < NREP * MNBR; idx += NTH) {
        int r = idx / MNBR, k = idx - r * MNBR;
        float v = aug[((size_t)r * n_loc + n) * (MNBR + 1) + 1 + k];
        if (v != v) v = 0.0f;  // NaN -> 0
        XT[k * XSTR + r] = v * scal_s[k];
    }
    __syncthreads();

    // ---- raw gram diagonal: diag_s[i] = sum_k XT[k][i]^2 (conflict-free columns)
    if (tid < NREP) {
        float s = 0.0f;
        #pragma unroll 8
        for (int k = 0; k < MNBR; ++k) {
            float x = XT[k * XSTR + tid];
            s = fmaf(x, x, s);
        }
        diag_s[tid] = s;
    }
    __syncthreads();

    // ---- transform constants ----
    const float th3 = theta[3], th4 = theta[4], th5 = theta[5];
    const float ls   = __expf(th5) * 1.7320508075688772f;  // sqrt(2*1.5)
    const float ils2 = 1.0f / (ls * ls);
    const float sg   = __expf(__logf(scales[n]) * th4 + th3);
    const float sig2 = sg * sg;
    const float inug = 1.0f / nug[n];

    // ---- fused gram + transform + g-write, 128x64 column passes ----
    // thread -> microtile: ty in 0..31 covers all 128 rows, tx in 0..15 covers 64 cols
    const int tx = tid & 15, ty = tid >> 4;
    {
        float o[4][4];
        // pass A: cols 64..127. tile(1,1) (rows>=64) also goes to Ash (disjoint from XT).
        {
            const int i0 = ty * 4, j0 = 64 + tx * 4;
            gram_full(XT, i0, j0, o);
            xform_tile(o, i0, j0, diag_s, ils2, sig2, inug);
            store_tile_g(gout, i0, j0, o);
            if (i0 >= 64) store_tile_s(Ash, i0, j0, o);
        }
        // pass B: cols 0..63. rows>=64 store now; rows<64 overlap XT -> hold, sync, store.
        {
            const int i0 = ty * 4, j0 = tx * 4;
            gram_full(XT, i0, j0, o);
            xform_tile(o, i0, j0, diag_s, ils2, sig2, inug);
            store_tile_g(gout, i0, j0, o);
            if (i0 >= 64) store_tile_s(Ash, i0, j0, o);
            __syncthreads();      // all XT reads complete
            if (i0 < 64) store_tile_s(Ash, i0, j0, o);
        }
    }
    __syncthreads();

    // ---- blocked Cholesky, NB=32, in place on lower triangle of Ash ----
    const int lane = tid & 31, wid = tid >> 5;
    for (int p = 0; p < 4; ++p) {
        const int pb = p * 32;

        // (a) 32x32 diagonal block: warp 0, register/shuffle resident
        if (wid == 0) {
            float a[32];
            #pragma unroll
            for (int cc = 0; cc < 8; ++cc) {
                float4 v = *(const float4*)(Ash + (pb + lane) * ASTR + pb + 4 * cc);
                a[4*cc+0] = (4*cc+0 <= lane) ? v.x : 0.0f;
                a[4*cc+1] = (4*cc+1 <= lane) ? v.y : 0.0f;
                a[4*cc+2] = (4*cc+2 <= lane) ? v.z : 0.0f;
                a[4*cc+3] = (4*cc+3 <= lane) ? v.w : 0.0f;
            }
            #pragma unroll
            for (int j = 0; j < 32; ++j) {
                float ajj = __shfl_sync(0xffffffffu, a[j], j);
                float rd  = rsqrtf(ajj);
                if (lane == j)      { a[j] = ajj * rd; invd_s[j] = rd; }
                else if (lane > j)  { a[j] *= rd; }
                float t = a[j];
                #pragma unroll
                for (int k2 = j + 1; k2 < 32; ++k2) {
                    float lkj = __shfl_sync(0xffffffffu, a[j], k2);
                    if (lane >= k2) a[k2] -= t * lkj;
                }
            }
            #pragma unroll
            for (int cc = 0; cc < 8; ++cc)
                *(float4*)(Ash + (pb + lane) * ASTR + pb + 4 * cc) =
                    make_float4(a[4*cc+0], a[4*cc+1], a[4*cc+2], a[4*cc+3]);
        }
        __syncthreads();

        const int q = pb + 32;
        const int mrows = 128 - q;
        if (mrows > 0) {
            // (b) TRSM: row-per-thread, row in registers, L00 via smem broadcast
            if (tid < mrows) {
                const int row = q + tid;
                float b[32];
                #pragma unroll
                for (int cc = 0; cc < 8; ++cc) {
                    float4 v = *(const float4*)(Ash + row * ASTR + pb + 4 * cc);
                    b[4*cc+0] = v.x; b[4*cc+1] = v.y; b[4*cc+2] = v.z; b[4*cc+3] = v.w;
                }
                #pragma unroll
                for (int j = 0; j < 32; ++j) {
                    b[j] *= invd_s[j];
                    float bj = b[j];
                    #pragma unroll
                    for (int k2 = j + 1; k2 < 32; ++k2)
                        b[k2] -= bj * Ash[(pb + k2) * ASTR + pb + j];
                }
                #pragma unroll
                for (int cc = 0; cc < 8; ++cc)
                    *(float4*)(Ash + row * ASTR + pb + 4 * cc) =
                        make_float4(b[4*cc+0], b[4*cc+1], b[4*cc+2], b[4*cc+3]);
            }
            __syncthreads();

            // (c) Schur: A22 -= L21 L21^T, lower triangle, 4x4 microtiles, FFMA2
            const int G = mrows >> 2;              // 24, 16, 8
            const int T = (G / 2) * (G + 1);       // G(G+1)/2
            for (int t = tid; t < T; t += NTH) {
                int u = t / (G + 1);
                int v = t - u * (G + 1);
                int mi, mj;
                if (v <= u) { mi = u; mj = v; }
                else        { mi = G - 1 - u; mj = v - u - 1; }
                const int i0 = q + mi * 4, j0 = q + mj * 4;
                unsigned long long acc2[4][2];
                #pragma unroll
                for (int r = 0; r < 4; ++r) { acc2[r][0] = 0ull; acc2[r][1] = 0ull; }
                #pragma unroll
                for (int kk = 0; kk < 32; kk += 4) {
                    float4 av[4], bv[4];
                    #pragma unroll
                    for (int r = 0; r < 4; ++r)
                        av[r] = *(const float4*)(Ash + (i0 + r) * ASTR + pb + kk);
                    #pragma unroll
                    for (int c = 0; c < 4; ++c)
                        bv[c] = *(const float4*)(Ash + (j0 + c) * ASTR + pb + kk);
                    {
                        unsigned long long b0 = pack2(bv[0].x, bv[1].x), b1 = pack2(bv[2].x, bv[3].x);
                        unsigned long long a0 = dup2(av[0].x), a1 = dup2(av[1].x), a2 = dup2(av[2].x), a3 = dup2(av[3].x);
                        ffma2(acc2[0][0], a0, b0); ffma2(acc2[0][1], a0, b1);
                        ffma2(acc2[1][0], a1, b0); ffma2(acc2[1][1], a1, b1);
                        ffma2(acc2[2][0], a2, b0); ffma2(acc2[2][1], a2, b1);
                        ffma2(acc2[3][0], a3, b0); ffma2(acc2[3][1], a3, b1);
                    }
                    {
                        unsigned long long b0 = pack2(bv[0].y, bv[1].y), b1 = pack2(bv[2].y, bv[3].y);
                        unsigned long long a0 = dup2(av[0].y), a1 = dup2(av[1].y), a2 = dup2(av[2].y), a3 = dup2(av[3].y);
                        ffma2(acc2[0][0], a0, b0); ffma2(acc2[0][1], a0, b1);
                        ffma2(acc2[1][0], a1, b0); ffma2(acc2[1][1], a1, b1);
                        ffma2(acc2[2][0], a2, b0); ffma2(acc2[2][1], a2, b1);
                        ffma2(acc2[3][0], a3, b0); ffma2(acc2[3][1], a3, b1);
                    }
                    {
                        unsigned long long b0 = pack2(bv[0].z, bv[1].z), b1 = pack2(bv[2].z, bv[3].z);
                        unsigned long long a0 = dup2(av[0].z), a1 = dup2(av[1].z), a2 = dup2(av[2].z), a3 = dup2(av[3].z);
                        ffma2(acc2[0][0], a0, b0); ffma2(acc2[0][1], a0, b1);
                        ffma2(acc2[1][0], a1, b0); ffma2(acc2[1][1], a1, b1);
                        ffma2(acc2[2][0], a2, b0); ffma2(acc2[2][1], a2, b1);
                        ffma2(acc2[3][0], a3, b0); ffma2(acc2[3][1], a3, b1);
                    }
                    {
                        unsigned long long b0 = pack2(bv[0].w, bv[1].w), b1 = pack2(bv[2].w, bv[3].w);
                        unsigned long long a0 = dup2(av[0].w), a1 = dup2(av[1].w), a2 = dup2(av[2].w), a3 = dup2(av[3].w);
                        ffma2(acc2[0][0], a0, b0); ffma2(acc2[0][1], a0, b1);
                        ffma2(acc2[1][0], a1, b0); ffma2(acc2[1][1], a1, b1);
                        ffma2(acc2[2][0], a2, b0); ffma2(acc2[2][1], a2, b1);
                        ffma2(acc2[3][0], a3, b0); ffma2(acc2[3][1], a3, b1);
                    }
                }
                #pragma unroll
                for (int r = 0; r < 4; ++r) {
                    float s0, s1, s2, s3;
                    unpack2(acc2[r][0], s0, s1);
                    unpack2(acc2[r][1], s2, s3);
                    float4* dst = (float4*)(Ash + (i0 + r) * ASTR + j0);
                    float4 d = *dst;
                    d.x -= s0; d.y -= s1; d.z -= s2; d.w -= s3;
                    *dst = d;
                }
            }
        }
        __syncthreads();
    }

    // ---- write chol (lower; zeros above), float4 coalesced ----
    for (int q4 = tid; q4 < 4096; q4 += NTH) {
        int idx = q4 * 4;
        int i = idx >> 7, j = idx & 127;
        float4 s = *(const float4*)(Ash + i * ASTR + j);
        float4 v;
        v.x = (j     <= i) ? s.x : 0.0f;
        v.y = (j + 1 <= i) ? s.y : 0.0f;
        v.z = (j + 2 <= i) ? s.z : 0.0f;
        v.w = (j + 3 <= i) ? s.w : 0.0f;
        ((float4*)cout)[q4] = v;
    }
}

extern "C" void kernel_launch(void* const* d_in, const int* in_sizes, int n_in,
                              void* d_out, int out_size)
{
    const float* aug    = (const float*)d_in[0];
    const float* theta  = (const float*)d_in[1];
    const float* scales = (const float*)d_in[2];
    const float* nug    = (const float*)d_in[3];
    const int*   bidx   = (const int*)d_in[4];
    const int n_loc = in_sizes[2];

    const size_t smem = SMEM_FLOATS * sizeof(float);
    cudaFuncSetAttribute(tmap_kernel, cudaFuncAttributeMaxDynamicSharedMemorySize, (int)smem);
    tmap_kernel<<<n_loc, NTH, smem>>>(aug, theta, scales, nug, bidx, (float*)d_out, n_loc);
}

// round 14
// speedup vs baseline: 2.1745x; 2.1745x over previous
#include <cuda_runtime.h>
#include <math.h>

#define NREP 128
#define MNBR 48
#define NTH  256
#define ASTR 132          // multiple of 4 -> 16B-aligned rows -> float4 LDS/STS
#define XSTR 132          // equals ASTR: XT aliases Ash rows 0..47 exactly

// shared layout (float offsets)
#define OFF_A    0
#define OFF_DIAG 16896    // 128*132
#define OFF_INVD 17024
#define SMEM_FLOATS 17056 // 68.2 KB -> 3 CTAs/SM @ 256 thr

__device__ __forceinline__ unsigned long long dup2(float x) {
    unsigned long long r;
    asm("mov.b64 %0, {%1, %1};" : "=l"(r) : "r"(__float_as_uint(x)));
    return r;
}
__device__ __forceinline__ unsigned long long pack2(float x, float y) {
    unsigned long long r;
    asm("mov.b64 %0, {%1, %2};" : "=l"(r) : "r"(__float_as_uint(x)), "r"(__float_as_uint(y)));
    return r;
}
__device__ __forceinline__ void unpack2(unsigned long long v, float &x, float &y) {
    unsigned lo, hi;
    asm("mov.b64 {%0, %1}, %2;" : "=r"(lo), "=r"(hi) : "l"(v));
    x = __uint_as_float(lo); y = __uint_as_float(hi);
}
// packed dual-FMA (sm_103a FFMA2) -- 2x fp32 throughput vs scalar FFMA
__device__ __forceinline__ void ffma2(unsigned long long &d, unsigned long long a, unsigned long long b) {
    asm("fma.rn.f32x2 %0, %1, %2, %3;" : "=l"(d) : "l"(a), "l"(b), "l"(d));
}

// 4x4 microtile gram over K=48, 8 independent packed accumulators
__device__ __forceinline__ void gram_full(const float* __restrict__ XT, int i0, int j0,
                                          float o[4][4]) {
    unsigned long long acc[4][2];
    #pragma unroll
    for (int r = 0; r < 4; ++r) { acc[r][0] = 0ull; acc[r][1] = 0ull; }
    #pragma unroll
    for (int k = 0; k < MNBR; ++k) {
        const float* row = XT + k * XSTR;
        float4 a4 = *(const float4*)(row + i0);
        float4 b4 = *(const float4*)(row + j0);
        unsigned long long bu0 = pack2(b4.x, b4.y);
        unsigned long long bu1 = pack2(b4.z, b4.w);
        unsigned long long a0 = dup2(a4.x), a1 = dup2(a4.y);
        unsigned long long a2 = dup2(a4.z), a3 = dup2(a4.w);
        ffma2(acc[0][0], a0, bu0); ffma2(acc[0][1], a0, bu1);
        ffma2(acc[1][0], a1, bu0); ffma2(acc[1][1], a1, bu1);
        ffma2(acc[2][0], a2, bu0); ffma2(acc[2][1], a2, bu1);
        ffma2(acc[3][0], a3, bu0); ffma2(acc[3][1], a3, bu1);
    }
    #pragma unroll
    for (int r = 0; r < 4; ++r) {
        unpack2(acc[r][0], o[r][0], o[r][1]);
        unpack2(acc[r][1], o[r][2], o[r][3]);
    }
}

extern "C" __global__ void __launch_bounds__(NTH, 3)
tmap_kernel(const float* __restrict__ aug,
            const float* __restrict__ theta,
            const float* __restrict__ scales,
            const float* __restrict__ nug,
            const int*   __restrict__ bidx,
            float* __restrict__ out,
            int n_loc)
{
    extern __shared__ float sm[];
    float* Ash    = sm + OFF_A;
    float* XT     = sm + OFF_A;      // aliased with Ash rows 0..47
    float* diag_s = sm + OFF_DIAG;
    float* invd_s = sm + OFF_INVD;

    const int n   = blockIdx.x;
    const int tid = threadIdx.x;
    float* gout = out + (size_t)n * 16384;
    float* cout = out + (size_t)n_loc * 16384 + (size_t)n * 16384;

    // batch_idx == 0  ->  g = I, chol = I
    if (bidx[n] == 0) {
        for (int q4 = tid; q4 < 4096; q4 += NTH) {
            int idx = q4 * 4;
            int i = idx >> 7, j = idx & 127;
            float4 v = make_float4(i == j ? 1.f : 0.f, i == j + 1 ? 1.f : 0.f,
                                   i == j + 2 ? 1.f : 0.f, i == j + 3 ? 1.f : 0.f);
            ((float4*)gout)[q4] = v;
            ((float4*)cout)[q4] = v;
        }
        return;
    }

    // ---- load xs transposed: XT[k][r] = aug[r,n,k+1] * exp(-0.5*(k+1)*e2) ----
    // fully unrolled -> 24 outstanding LDGs; per-element __expf (MUFU, overlaps LDG)
    {
        const float e2 = __expf(theta[2]);
        #pragma unroll
        for (int it = 0; it < 24; ++it) {
            int idx = tid + it * NTH;           // < 6144 exactly
            int r = idx / MNBR, k = idx - r * MNBR;
            float v = aug[((size_t)r * n_loc + n) * (MNBR + 1) + 1 + k];
            if (v != v) v = 0.0f;               // NaN -> 0
            XT[k * XSTR + r] = v * __expf(-0.5f * (float)(k + 1) * e2);
        }
    }
    __syncthreads();

    // ---- raw gram diagonal: diag_s[i] = sum_k XT[k][i]^2 ----
    if (tid < NREP) {
        float s = 0.0f;
        #pragma unroll 8
        for (int k = 0; k < MNBR; ++k) {
            float x = XT[k * XSTR + tid];
            s = fmaf(x, x, s);
        }
        diag_s[tid] = s;
    }
    __syncthreads();

    // ---- transform constants ----
    const float th3 = theta[3], th4 = theta[4], th5 = theta[5];
    const float ls   = __expf(th5) * 1.7320508075688772f;   // sqrt(2*1.5)
    const float ils2 = 1.0f / (ls * ls);
    const float sg   = __expf(__logf(scales[n]) * th4 + th3);
    const float sig2 = sg * sg;
    const float inug = 1.0f / nug[n];

    // ---- fused gram + Matern transform + g STG; Ash rows>=48 stored directly ----
    {
        const int rt = tid >> 3, ct = tid & 7;   // 32 row-tiles x 8 col-tiles
        const int i0 = rt * 4;
        float4 di4 = *(const float4*)(diag_s + i0);
        float di[4] = {di4.x, di4.y, di4.z, di4.w};
        for (int cg = 0; cg < 4; ++cg) {
            const int j0 = cg * 32 + ct * 4;
            float o[4][4];
            gram_full(XT, i0, j0, o);
            float4 dj4 = *(const float4*)(diag_s + j0);
            float dj[4] = {dj4.x, dj4.y, dj4.z, dj4.w};
            #pragma unroll
            for (int r = 0; r < 4; ++r) {
                #pragma unroll
                for (int c = 0; c < 4; ++c) {
                    float lin = o[r][c];
                    float sq  = (di[r] + dj[c] - 2.0f * lin) * ils2;
                    float d   = sqrtf(fmaxf(sq, 0.0f));
                    float s3  = 1.7320508075688772f * d;
                    float mat = (1.0f + s3) * __expf(-s3);
                    float val = (lin + sig2 * mat) * inug;
                    if (i0 + r == j0 + c) val += 1.0f;
                    o[r][c] = val;
                }
            }
            #pragma unroll
            for (int r = 0; r < 4; ++r) {
                float4 v = make_float4(o[r][0], o[r][1], o[r][2], o[r][3]);
                *(float4*)(gout + (i0 + r) * 128 + j0) = v;
                if (i0 >= 48) *(float4*)(Ash + (i0 + r) * ASTR + j0) = v;
            }
        }
    }
    __syncthreads();   // XT dead; gout rows 0..47 fully written & visible in-block

    // ---- read back g rows 0..47 from gmem (L2-hot) into Ash ----
    for (int t = tid; t < 1536; t += NTH) {    // 48 rows x 32 float4
        int r = t >> 5, c4 = (t & 31) * 4;
        *(float4*)(Ash + r * ASTR + c4) = *(const float4*)(gout + r * 128 + c4);
    }
    __syncthreads();

    // ---- blocked Cholesky, NB=32, lower triangle of Ash in place ----
    // transposed L21 panel Lp[k][m] lives in dead upper triangle: Ash[k][32+m]
    const int lane = tid & 31, wid = tid >> 5;
    for (int p = 0; p < 4; ++p) {
        const int pb = p * 32;

        // (a) 32x32 diagonal block: warp 0, register/shuffle resident
        if (wid == 0) {
            float a[32];
            #pragma unroll
            for (int cc = 0; cc < 8; ++cc) {
                float4 v = *(const float4*)(Ash + (pb + lane) * ASTR + pb + 4 * cc);
                a[4*cc+0] = (4*cc+0 <= lane) ? v.x : 0.0f;
                a[4*cc+1] = (4*cc+1 <= lane) ? v.y : 0.0f;
                a[4*cc+2] = (4*cc+2 <= lane) ? v.z : 0.0f;
                a[4*cc+3] = (4*cc+3 <= lane) ? v.w : 0.0f;
            }
            #pragma unroll
            for (int j = 0; j < 32; ++j) {
                float ajj = __shfl_sync(0xffffffffu, a[j], j);
                float rd  = rsqrtf(ajj);
                if (lane == j)      { a[j] = ajj * rd; invd_s[j] = rd; }
                else if (lane > j)  { a[j] *= rd; }
                float t = a[j];
                #pragma unroll
                for (int k2 = j + 1; k2 < 32; ++k2) {
                    float lkj = __shfl_sync(0xffffffffu, a[j], k2);
                    if (lane >= k2) a[k2] -= t * lkj;
                }
            }
            #pragma unroll
            for (int cc = 0; cc < 8; ++cc)
                *(float4*)(Ash + (pb + lane) * ASTR + pb + 4 * cc) =
                    make_float4(a[4*cc+0], a[4*cc+1], a[4*cc+2], a[4*cc+3]);
        }
        __syncthreads();

        const int q = pb + 32;
        const int mrows = 128 - q;

        // (b) TRSM: row-per-thread; also store row transposed into Lp (contiguous STS)
        if (mrows > 0 && tid < mrows) {
            const int row = q + tid;
            float b[32];
            #pragma unroll
            for (int cc = 0; cc < 8; ++cc) {
                float4 v = *(const float4*)(Ash + row * ASTR + pb + 4 * cc);
                b[4*cc+0] = v.x; b[4*cc+1] = v.y; b[4*cc+2] = v.z; b[4*cc+3] = v.w;
            }
            #pragma unroll
            for (int j = 0; j < 32; ++j) {
                b[j] *= invd_s[j];
                float bj = b[j];
                #pragma unroll
                for (int k2 = j + 1; k2 < 32; ++k2)
                    b[k2] -= bj * Ash[(pb + k2) * ASTR + pb + j];
            }
            #pragma unroll
            for (int cc = 0; cc < 8; ++cc)
                *(float4*)(Ash + row * ASTR + pb + 4 * cc) =
                    make_float4(b[4*cc+0], b[4*cc+1], b[4*cc+2], b[4*cc+3]);
            #pragma unroll
            for (int k2 = 0; k2 < 32; ++k2)       // Lp[k2][tid]
                Ash[k2 * ASTR + 32 + tid] = b[k2];
        }
        __syncthreads();

        // write chol block-column [0..127] x [pb..pb+31] (final after TRSM)
        for (int t = tid; t < 1024; t += NTH) {   // 128 rows x 8 float4
            int row = t >> 3, j = pb + (t & 7) * 4;
            float4 v = make_float4(0.f, 0.f, 0.f, 0.f);
            if (row >= pb) {
                float4 s = *(const float4*)(Ash + row * ASTR + j);
                v.x = (j     <= row) ? s.x : 0.0f;
                v.y = (j + 1 <= row) ? s.y : 0.0f;
                v.z = (j + 2 <= row) ? s.z : 0.0f;
                v.w = (j + 3 <= row) ? s.w : 0.0f;
            }
            *(float4*)(cout + row * 128 + j) = v;
        }

        // (c) Schur: A22 -= L21 L21^T via Lp (conflict-free, gram-style)
        if (mrows > 0) {
            const int G = mrows >> 2;              // 24, 16, 8
            const int T = (G / 2) * (G + 1);       // G(G+1)/2
            for (int t = tid; t < T; t += NTH) {
                int u = t / (G + 1);
                int v = t - u * (G + 1);
                int mi, mj;
                if (v <= u) { mi = u; mj = v; }
                else        { mi = G - 1 - u; mj = v - u - 1; }
                const int ia = 32 + mi * 4, ja = 32 + mj * 4;   // Lp col offsets
                unsigned long long acc[4][2];
                #pragma unroll
                for (int r = 0; r < 4; ++r) { acc[r][0] = 0ull; acc[r][1] = 0ull; }
                #pragma unroll 8
                for (int k = 0; k < 32; ++k) {
                    const float* lr = Ash + k * ASTR;
                    float4 a4 = *(const float4*)(lr + ia);
                    float4 b4 = *(const float4*)(lr + ja);
                    unsigned long long bu0 = pack2(b4.x, b4.y);
                    unsigned long long bu1 = pack2(b4.z, b4.w);
                    unsigned long long a0 = dup2(a4.x), a1 = dup2(a4.y);
                    unsigned long long a2 = dup2(a4.z), a3 = dup2(a4.w);
                    ffma2(acc[0][0], a0, bu0); ffma2(acc[0][1], a0, bu1);
                    ffma2(acc[1][0], a1, bu0); ffma2(acc[1][1], a1, bu1);
                    ffma2(acc[2][0], a2, bu0); ffma2(acc[2][1], a2, bu1);
                    ffma2(acc[3][0], a3, bu0); ffma2(acc[3][1], a3, bu1);
                }
                const int i0 = q + mi * 4, j0 = q + mj * 4;
                #pragma unroll
                for (int r = 0; r < 4; ++r) {
                    float s0, s1, s2, s3;
                    unpack2(acc[r][0], s0, s1);
                    unpack2(acc[r][1], s2, s3);
                    float4* dst = (float4*)(Ash + (i0 + r) * ASTR + j0);
                    float4 d = *dst;
                    d.x -= s0; d.y -= s1; d.z -= s2; d.w -= s3;
                    *dst = d;
                }
            }
        }
        __syncthreads();
    }
}

extern "C" void kernel_launch(void* const* d_in, const int* in_sizes, int n_in,
                              void* d_out, int out_size)
{
    const float* aug    = (const float*)d_in[0];
    const float* theta  = (const float*)d_in[1];
    const float* scales = (const float*)d_in[2];
    const float* nug    = (const float*)d_in[3];
    const int*   bidx   = (const int*)d_in[4];
    const int n_loc = in_sizes[2];

    const size_t smem = SMEM_FLOATS * sizeof(float);
    cudaFuncSetAttribute(tmap_kernel, cudaFuncAttributeMaxDynamicSharedMemorySize, (int)smem);
    tmap_kernel<<<n_loc, NTH, smem>>>(aug, theta, scales, nug, bidx, (float*)d_out, n_loc);
}

// round 17
// speedup vs baseline: 2.2947x; 1.0553x over previous
#include <cuda_runtime.h>
#include <math.h>

#define NREP 128
#define MNBR 48
#define NTH  256
#define ASTR 132          // multiple of 4 -> 16B-aligned rows -> float4 LDS/STS
#define XSTR 132          // equals ASTR: XT aliases Ash rows 0..47 exactly

// shared layout (float offsets)
#define OFF_A    0
#define OFF_DIAG 16896    // 128*132
#define OFF_INVD 17024
#define SMEM_FLOATS 17056 // 68.2 KB -> 3 CTAs/SM @ 256 thr

__device__ __forceinline__ unsigned long long dup2(float x) {
    unsigned long long r;
    asm("mov.b64 %0, {%1, %1};" : "=l"(r) : "r"(__float_as_uint(x)));
    return r;
}
__device__ __forceinline__ unsigned long long pack2(float x, float y) {
    unsigned long long r;
    asm("mov.b64 %0, {%1, %2};" : "=l"(r) : "r"(__float_as_uint(x)), "r"(__float_as_uint(y)));
    return r;
}
__device__ __forceinline__ void unpack2(unsigned long long v, float &x, float &y) {
    unsigned lo, hi;
    asm("mov.b64 {%0, %1}, %2;" : "=r"(lo), "=r"(hi) : "l"(v));
    x = __uint_as_float(lo); y = __uint_as_float(hi);
}
// packed dual-FMA (sm_103a FFMA2) -- 2x fp32 throughput vs scalar FFMA
__device__ __forceinline__ void ffma2(unsigned long long &d, unsigned long long a, unsigned long long b) {
    asm("fma.rn.f32x2 %0, %1, %2, %3;" : "=l"(d) : "l"(a), "l"(b), "l"(d));
}

// single-MUFU approx sqrt (sqrt.approx(+0)=+0)
__device__ __forceinline__ float fast_sqrt(float x) {
    float r; asm("sqrt.approx.f32 %0, %1;" : "=f"(r) : "f"(x)); return r;
}

// e^{-x} for x >= 0, MUFU-free: exp2 range reduction + degree-7 FMA poly.
// |rel err| ~ 5e-9 (poly) + rounding; underflows cleanly past x ~ 83.
__device__ __forceinline__ float fast_expneg(float x) {
    float t = x * -1.4426950408889634f;          // -x*log2(e) <= 0
    t = fmaxf(t, -120.0f);                       // keep exponent math in range
    float fn = rintf(t);
    float f  = t - fn;                           // |f| <= 0.5
    float g  = f * 0.6931471805599453f;          // |g| <= 0.3466
    float p  = 1.98412698412e-4f;                // 1/5040
    p = fmaf(p, g, 1.38888888889e-3f);           // 1/720
    p = fmaf(p, g, 8.33333333333e-3f);           // 1/120
    p = fmaf(p, g, 4.16666666667e-2f);           // 1/24
    p = fmaf(p, g, 1.66666666667e-1f);           // 1/6
    p = fmaf(p, g, 0.5f);
    p = fmaf(p, g, 1.0f);
    p = fmaf(p, g, 1.0f);
    int ni = (int)fn;
    return __int_as_float(__float_as_int(p) + ni * 8388608); // p * 2^ni
}

// 4x4 microtile gram over K=48, 8 independent packed accumulators
__device__ __forceinline__ void gram_full(const float* __restrict__ XT, int i0, int j0,
                                          float o[4][4]) {
    unsigned long long acc[4][2];
    #pragma unroll
    for (int r = 0; r < 4; ++r) { acc[r][0] = 0ull; acc[r][1] = 0ull; }
    #pragma unroll
    for (int k = 0; k < MNBR; ++k) {
        const float* row = XT + k * XSTR;
        float4 a4 = *(const float4*)(row + i0);
        float4 b4 = *(const float4*)(row + j0);
        unsigned long long bu0 = pack2(b4.x, b4.y);
        unsigned long long bu1 = pack2(b4.z, b4.w);
        unsigned long long a0 = dup2(a4.x), a1 = dup2(a4.y);
        unsigned long long a2 = dup2(a4.z), a3 = dup2(a4.w);
        ffma2(acc[0][0], a0, bu0); ffma2(acc[0][1], a0, bu1);
        ffma2(acc[1][0], a1, bu0); ffma2(acc[1][1], a1, bu1);
        ffma2(acc[2][0], a2, bu0); ffma2(acc[2][1], a2, bu1);
        ffma2(acc[3][0], a3, bu0); ffma2(acc[3][1], a3, bu1);
    }
    #pragma unroll
    for (int r = 0; r < 4; ++r) {
        unpack2(acc[r][0], o[r][0], o[r][1]);
        unpack2(acc[r][1], o[r][2], o[r][3]);
    }
}

extern "C" __global__ void __launch_bounds__(NTH, 3)
tmap_kernel(const float* __restrict__ aug,
            const float* __restrict__ theta,
            const float* __restrict__ scales,
            const float* __restrict__ nug,
            const int*   __restrict__ bidx,
            float* __restrict__ out,
            int n_loc)
{
    extern __shared__ float sm[];
    float* Ash    = sm + OFF_A;
    float* XT     = sm + OFF_A;      // aliased with Ash rows 0..47
    float* diag_s = sm + OFF_DIAG;
    float* invd_s = sm + OFF_INVD;

    const int n   = blockIdx.x;
    const int tid = threadIdx.x;
    float* gout = out + (size_t)n * 16384;
    float* cout = out + (size_t)n_loc * 16384 + (size_t)n * 16384;

    // batch_idx == 0  ->  g = I, chol = I
    if (bidx[n] == 0) {
        for (int q4 = tid; q4 < 4096; q4 += NTH) {
            int idx = q4 * 4;
            int i = idx >> 7, j = idx & 127;
            float4 v = make_float4(i == j ? 1.f : 0.f, i == j + 1 ? 1.f : 0.f,
                                   i == j + 2 ? 1.f : 0.f, i == j + 3 ? 1.f : 0.f);
            ((float4*)gout)[q4] = v;
            ((float4*)cout)[q4] = v;
        }
        return;
    }

    // ---- load xs transposed: XT[k][r] = aug[r,n,k+1] * exp(-0.5*(k+1)*e2) ----
    {
        const float e2 = __expf(theta[2]);
        #pragma unroll
        for (int it = 0; it < 24; ++it) {
            int idx = tid + it * NTH;           // < 6144 exactly
            int r = idx / MNBR, k = idx - r * MNBR;
            float v = aug[((size_t)r * n_loc + n) * (MNBR + 1) + 1 + k];
            if (v != v) v = 0.0f;               // NaN -> 0
            XT[k * XSTR + r] = v * __expf(-0.5f * (float)(k + 1) * e2);
        }
    }
    __syncthreads();

    // ---- raw gram diagonal: diag_s[i] = sum_k XT[k][i]^2 ----
    if (tid < NREP) {
        float s = 0.0f;
        #pragma unroll 8
        for (int k = 0; k < MNBR; ++k) {
            float x = XT[k * XSTR + tid];
            s = fmaf(x, x, s);
        }
        diag_s[tid] = s;
    }
    __syncthreads();

    // ---- transform constants ----
    const float th3 = theta[3], th4 = theta[4], th5 = theta[5];
    const float ls   = __expf(th5) * 1.7320508075688772f;   // sqrt(2*1.5)
    const float c3   = 3.0f / (ls * ls);                    // 3*ils2 (fold sqrt(3) in)
    const float sg   = __expf(__logf(scales[n]) * th4 + th3);
    const float sig2 = sg * sg;
    const float inug = 1.0f / nug[n];

    // ---- fused gram + Matern transform on LOWER tiles only; mirror STG ----
    // 32x32 tile grid, 528 lower tiles, rectangle-pair decode (u pairs 31-u)
    for (int t = tid; t < 528; t += NTH) {
        int u = t / 33;
        int v = t - u * 33;
        int mi, mj;
        if (v <= u) { mi = u; mj = v; }
        else        { mi = 31 - u; mj = v - u - 1; }
        const int i0 = mi * 4, j0 = mj * 4;

        float o[4][4];
        gram_full(XT, i0, j0, o);

        float4 di4 = *(const float4*)(diag_s + i0);
        float4 dj4 = *(const float4*)(diag_s + j0);
        float di[4] = {di4.x, di4.y, di4.z, di4.w};
        float dj[4] = {dj4.x, dj4.y, dj4.z, dj4.w};
        #pragma unroll
        for (int r = 0; r < 4; ++r) {
            #pragma unroll
            for (int c = 0; c < 4; ++c) {
                float lin = o[r][c];
                float sq3 = fmaxf((di[r] + dj[c] - 2.0f * lin) * c3, 0.0f);
                float s3  = fast_sqrt(sq3);                 // 1 MUFU
                float mat = (1.0f + s3) * fast_expneg(s3);  // 0 MUFU
                float val = (lin + sig2 * mat) * inug;
                if (i0 + r == j0 + c) val += 1.0f;
                o[r][c] = val;
            }
        }
        // tile STG (row float4s)
        #pragma unroll
        for (int r = 0; r < 4; ++r)
            *(float4*)(gout + (i0 + r) * 128 + j0) =
                make_float4(o[r][0], o[r][1], o[r][2], o[r][3]);
        // mirror STG (transposed) for strictly-lower tiles
        if (mi != mj) {
            #pragma unroll
            for (int c = 0; c < 4; ++c)
                *(float4*)(gout + (j0 + c) * 128 + i0) =
                    make_float4(o[0][c], o[1][c], o[2][c], o[3][c]);
        }
        // Ash store for chol (rows >= 48 don't overlap XT)
        if (i0 >= 48) {
            #pragma unroll
            for (int r = 0; r < 4; ++r)
                *(float4*)(Ash + (i0 + r) * ASTR + j0) =
                    make_float4(o[r][0], o[r][1], o[r][2], o[r][3]);
        }
    }
    __syncthreads();   // XT dead; gout rows 0..47 complete & block-visible

    // ---- read back rows 0..47, cols 0..47 from gmem (covers their lower tri) ----
    for (int t = tid; t < 576; t += NTH) {     // 48 rows x 12 float4
        int r = t / 12, c4 = (t - r * 12) * 4;
        *(float4*)(Ash + r * ASTR + c4) = *(const float4*)(gout + r * 128 + c4);
    }
    __syncthreads();

    // ---- blocked Cholesky, NB=32, lower triangle of Ash in place ----
    // transposed L21 panel Lp[k][m] lives in dead upper triangle: Ash[k][32+m]
    const int lane = tid & 31, wid = tid >> 5;
    for (int p = 0; p < 4; ++p) {
        const int pb = p * 32;

        // (a) 32x32 diagonal block: warp 0, register/shuffle resident
        if (wid == 0) {
            float a[32];
            #pragma unroll
            for (int cc = 0; cc < 8; ++cc) {
                float4 v = *(const float4*)(Ash + (pb + lane) * ASTR + pb + 4 * cc);
                a[4*cc+0] = (4*cc+0 <= lane) ? v.x : 0.0f;
                a[4*cc+1] = (4*cc+1 <= lane) ? v.y : 0.0f;
                a[4*cc+2] = (4*cc+2 <= lane) ? v.z : 0.0f;
                a[4*cc+3] = (4*cc+3 <= lane) ? v.w : 0.0f;
            }
            #pragma unroll
            for (int j = 0; j < 32; ++j) {
                float ajj = __shfl_sync(0xffffffffu, a[j], j);
                float rd  = rsqrtf(ajj);
                if (lane == j)      { a[j] = ajj * rd; invd_s[j] = rd; }
                else if (lane > j)  { a[j] *= rd; }
                float t2 = a[j];
                #pragma unroll
                for (int k2 = j + 1; k2 < 32; ++k2) {
                    float lkj = __shfl_sync(0xffffffffu, a[j], k2);
                    if (lane >= k2) a[k2] -= t2 * lkj;
                }
            }
            #pragma unroll
            for (int cc = 0; cc < 8; ++cc)
                *(float4*)(Ash + (pb + lane) * ASTR + pb + 4 * cc) =
                    make_float4(a[4*cc+0], a[4*cc+1], a[4*cc+2], a[4*cc+3]);
        }
        __syncthreads();

        const int q = pb + 32;
        const int mrows = 128 - q;

        // (b) TRSM: row-per-thread; store row transposed into Lp (contiguous STS)
        if (mrows > 0 && tid < mrows) {
            const int row = q + tid;
            float b[32];
            #pragma unroll
            for (int cc = 0; cc < 8; ++cc) {
                float4 v = *(const float4*)(Ash + row * ASTR + pb + 4 * cc);
                b[4*cc+0] = v.x; b[4*cc+1] = v.y; b[4*cc+2] = v.z; b[4*cc+3] = v.w;
            }
            #pragma unroll
            for (int j = 0; j < 32; ++j) {
                b[j] *= invd_s[j];
                float bj = b[j];
                #pragma unroll
                for (int k2 = j + 1; k2 < 32; ++k2)
                    b[k2] -= bj * Ash[(pb + k2) * ASTR + pb + j];
            }
            #pragma unroll
            for (int cc = 0; cc < 8; ++cc)
                *(float4*)(Ash + row * ASTR + pb + 4 * cc) =
                    make_float4(b[4*cc+0], b[4*cc+1], b[4*cc+2], b[4*cc+3]);
            #pragma unroll
            for (int k2 = 0; k2 < 32; ++k2)       // Lp[k2][tid]
                Ash[k2 * ASTR + 32 + tid] = b[k2];
        }
        __syncthreads();

        // write chol block-column [0..127] x [pb..pb+31] (final after TRSM)
        for (int t = tid; t < 1024; t += NTH) {   // 128 rows x 8 float4
            int row = t >> 3, j = pb + (t & 7) * 4;
            float4 v = make_float4(0.f, 0.f, 0.f, 0.f);
            if (row >= pb) {
                float4 s = *(const float4*)(Ash + row * ASTR + j);
                v.x = (j     <= row) ? s.x : 0.0f;
                v.y = (j + 1 <= row) ? s.y : 0.0f;
                v.z = (j + 2 <= row) ? s.z : 0.0f;
                v.w = (j + 3 <= row) ? s.w : 0.0f;
            }
            *(float4*)(cout + row * 128 + j) = v;
        }

        // (c) Schur: A22 -= L21 L21^T via Lp (conflict-free, gram-style)
        if (mrows > 0) {
            const int G = mrows >> 2;              // 24, 16, 8
            const int T = (G / 2) * (G + 1);       // G(G+1)/2
            for (int t = tid; t < T; t += NTH) {
                int u = t / (G + 1);
                int v = t - u * (G + 1);
                int mi, mj;
                if (v <= u) { mi = u; mj = v; }
                else        { mi = G - 1 - u; mj = v - u - 1; }
                const int ia = 32 + mi * 4, ja = 32 + mj * 4;   // Lp col offsets
                unsigned long long acc[4][2];
                #pragma unroll
                for (int r = 0; r < 4; ++r) { acc[r][0] = 0ull; acc[r][1] = 0ull; }
                #pragma unroll 8
                for (int k = 0; k < 32; ++k) {
                    const float* lr = Ash + k * ASTR;
                    float4 a4 = *(const float4*)(lr + ia);
                    float4 b4 = *(const float4*)(lr + ja);
                    unsigned long long bu0 = pack2(b4.x, b4.y);
                    unsigned long long bu1 = pack2(b4.z, b4.w);
                    unsigned long long a0 = dup2(a4.x), a1 = dup2(a4.y);
                    unsigned long long a2 = dup2(a4.z), a3 = dup2(a4.w);
                    ffma2(acc[0][0], a0, bu0); ffma2(acc[0][1], a0, bu1);
                    ffma2(acc[1][0], a1, bu0); ffma2(acc[1][1], a1, bu1);
                    ffma2(acc[2][0], a2, bu0); ffma2(acc[2][1], a2, bu1);
                    ffma2(acc[3][0], a3, bu0); ffma2(acc[3][1], a3, bu1);
                }
                const int i0 = q + mi * 4, j0 = q + mj * 4;
                #pragma unroll
                for (int r = 0; r < 4; ++r) {
                    float s0, s1, s2, s3;
                    unpack2(acc[r][0], s0, s1);
                    unpack2(acc[r][1], s2, s3);
                    float4* dst = (float4*)(Ash + (i0 + r) * ASTR + j0);
                    float4 d = *dst;
                    d.x -= s0; d.y -= s1; d.z -= s2; d.w -= s3;
                    *dst = d;
                }
            }
        }
        __syncthreads();
    }
}

extern "C" void kernel_launch(void* const* d_in, const int* in_sizes, int n_in,
                              void* d_out, int out_size)
{
    const float* aug    = (const float*)d_in[0];
    const float* theta  = (const float*)d_in[1];
    const float* scales = (const float*)d_in[2];
    const float* nug    = (const float*)d_in[3];
    const int*   bidx   = (const int*)d_in[4];
    const int n_loc = in_sizes[2];

    const size_t smem = SMEM_FLOATS * sizeof(float);
    cudaFuncSetAttribute(tmap_kernel, cudaFuncAttributeMaxDynamicSharedMemorySize, (int)smem);
    tmap_kernel<<<n_loc, NTH, smem>>>(aug, theta, scales, nug, bidx, (float*)d_out, n_loc);
}